// round 3
// baseline (speedup 1.0000x reference)
#include <cuda_runtime.h>
#include <cstdint>

#define BB   4
#define TT   8
#define NN   4096
#define CIN  64
#define C0V  64
#define C1V  128
#define MM   1024
#define KK   32

// ---------------- scratch (device globals; no allocation allowed) ----------------
__device__ int   g_aidx[BB*TT*MM];            // FPS anchor indices
__device__ int   g_ball[BB*TT*3*MM*KK];       // ball query indices      (12 MB)
__device__ float g_xf[(size_t)BB*TT*NN*C0V];  // relu(Wf . f) per point  (33.5 MB)

// exact (non-contracted) squared distance, matches XLA elementwise+reduce order
__device__ __forceinline__ float sq3(float dx, float dy, float dz) {
    return __fadd_rn(__fadd_rn(__fmul_rn(dx,dx), __fmul_rn(dy,dy)), __fmul_rn(dz,dz));
}

// ---------------- Kernel A: Xf[b,t,p,c0] = relu(sum_c Wf[c0,c] * feat[b,t,c,p]) ----
__global__ __launch_bounds__(256) void xf_kernel(const float* __restrict__ feat,
                                                 const float* __restrict__ Wf) {
    int bt = blockIdx.x;          // 0..31
    int p0 = blockIdx.y * 64;     // point tile
    __shared__ float sWfT[CIN*C0V];   // [c][o]
    __shared__ float sF[CIN*64];      // [c][p]
    int tid = threadIdx.x;
    for (int e = tid; e < CIN*C0V; e += 256) {
        int o = e / CIN, c = e % CIN;
        sWfT[c*C0V + o] = Wf[e];
    }
    const float* fb = feat + (size_t)bt*CIN*NN + p0;
    for (int e = tid; e < CIN*64; e += 256) {
        int c = e >> 6, p = e & 63;
        sF[e] = fb[(size_t)c*NN + p];
    }
    __syncthreads();
    float* xb = g_xf + ((size_t)bt*NN + p0)*C0V;
    #pragma unroll 4
    for (int r = 0; r < 16; r++) {
        int e = r*256 + tid;
        int p = e >> 6, o = e & 63;
        float s = 0.f;
        #pragma unroll
        for (int c = 0; c < CIN; c++)
            s = fmaf(sWfT[c*C0V + o], sF[c*64 + p], s);
        xb[(size_t)p*C0V + o] = fmaxf(s, 0.f);
    }
}

// ---------------- Kernel B: furthest point sampling, one block per (b, frame) ------
// Points live in registers (4 per thread). The argmax reduction carries the winning
// point's coordinates, so no point array in shared memory is needed at all.
__global__ __launch_bounds__(1024) void fps_kernel(const float* __restrict__ xyzs) {
    __shared__ float sWv[32], sWx[32], sWy[32], sWz[32];
    __shared__ int   sWi[32];
    __shared__ float sLx, sLy, sLz;
    int bt  = blockIdx.x;
    int tid = threadIdx.x;
    const float* xb = xyzs + (size_t)bt*NN*3;

    int   i0 = tid, i1 = tid+1024, i2 = tid+2048, i3 = tid+3072;
    float x0=xb[i0*3+0], y0=xb[i0*3+1], z0=xb[i0*3+2];
    float x1=xb[i1*3+0], y1=xb[i1*3+1], z1=xb[i1*3+2];
    float x2=xb[i2*3+0], y2=xb[i2*3+1], z2=xb[i2*3+2];
    float x3=xb[i3*3+0], y3=xb[i3*3+1], z3=xb[i3*3+2];
    float d0=1e10f, d1=1e10f, d2=1e10f, d3=1e10f;

    int* aout = g_aidx + bt*MM;
    if (tid == 0) {
        aout[0] = 0;
        sLx = xb[0]; sLy = xb[1]; sLz = xb[2];
    }
    int lane = tid & 31, wid = tid >> 5;
    __syncthreads();

    for (int it = 1; it < MM; it++) {
        float lx = sLx, ly = sLy, lz = sLz;
        d0 = fminf(d0, sq3(x0-lx, y0-ly, z0-lz));
        d1 = fminf(d1, sq3(x1-lx, y1-ly, z1-lz));
        d2 = fminf(d2, sq3(x2-lx, y2-ly, z2-lz));
        d3 = fminf(d3, sq3(x3-lx, y3-ly, z3-lz));
        // local argmax, first-occurrence tie-break (indices ascending: i0<i1<i2<i3)
        float bv = d0; int bi = i0; float bx = x0, by = y0, bz = z0;
        if (d1 > bv) { bv = d1; bi = i1; bx = x1; by = y1; bz = z1; }
        if (d2 > bv) { bv = d2; bi = i2; bx = x2; by = y2; bz = z2; }
        if (d3 > bv) { bv = d3; bi = i3; bx = x3; by = y3; bz = z3; }
        #pragma unroll
        for (int o = 16; o > 0; o >>= 1) {
            float ov = __shfl_down_sync(0xffffffffu, bv, o);
            int   oi = __shfl_down_sync(0xffffffffu, bi, o);
            float ox = __shfl_down_sync(0xffffffffu, bx, o);
            float oy = __shfl_down_sync(0xffffffffu, by, o);
            float oz = __shfl_down_sync(0xffffffffu, bz, o);
            if (ov > bv || (ov == bv && oi < bi)) { bv=ov; bi=oi; bx=ox; by=oy; bz=oz; }
        }
        if (lane == 0) { sWv[wid]=bv; sWi[wid]=bi; sWx[wid]=bx; sWy[wid]=by; sWz[wid]=bz; }
        __syncthreads();
        if (wid == 0) {
            float v = sWv[lane]; int ix = sWi[lane];
            float vx = sWx[lane], vy = sWy[lane], vz = sWz[lane];
            #pragma unroll
            for (int o = 16; o > 0; o >>= 1) {
                float ov = __shfl_down_sync(0xffffffffu, v, o);
                int   oi = __shfl_down_sync(0xffffffffu, ix, o);
                float ox = __shfl_down_sync(0xffffffffu, vx, o);
                float oy = __shfl_down_sync(0xffffffffu, vy, o);
                float oz = __shfl_down_sync(0xffffffffu, vz, o);
                if (ov > v || (ov == v && oi < ix)) { v=ov; ix=oi; vx=ox; vy=oy; vz=oz; }
            }
            if (lane == 0) { aout[it] = ix; sLx = vx; sLy = vy; sLz = vz; }
        }
        __syncthreads();
    }
}

// ---------------- Kernel E: write new_xyzs (anchor coords) -------------------------
__global__ __launch_bounds__(256) void anchor_kernel(const float* __restrict__ xyzs,
                                                     float* __restrict__ outxyz) {
    int idx = blockIdx.x*256 + threadIdx.x;
    if (idx >= BB*TT*MM) return;
    int bt = idx / MM;
    int a  = g_aidx[idx];
    const float* s = xyzs + ((size_t)bt*NN + a)*3;
    float* d = outxyz + (size_t)idx*3;
    d[0] = s[0]; d[1] = s[1]; d[2] = s[2];
}

// ---------------- Kernel C: ball query (warp per anchor, first-K ascending) --------
// dynamic smem = 49152 B exactly, no static smem in this kernel (48 KB limit OK)
__global__ __launch_bounds__(256) void ball_kernel(const float* __restrict__ xyzs) {
    extern __shared__ float sm[];           // frame ti points (48 KB)
    float* px = sm; float* py = sm + NN; float* pz = sm + 2*NN;
    int g  = blockIdx.x;                    // (b, to, i)
    int b  = g / (TT*3);
    int r  = g % (TT*3);
    int to = r / 3, i = r % 3;
    int ti = min(max(to + i - 1, 0), TT-1);
    int tid = threadIdx.x;
    const float* fb = xyzs + ((size_t)(b*TT+ti))*NN*3;
    for (int p = tid; p < NN; p += 256) {
        px[p] = fb[p*3+0]; py[p] = fb[p*3+1]; pz[p] = fb[p*3+2];
    }
    __syncthreads();
    const float RR = (float)(0.2*0.2);
    int warp = tid >> 5, lane = tid & 31;
    for (int mi = 0; mi < 32; mi++) {
        int m = (blockIdx.y*8 + warp)*32 + mi;
        int aidx = g_aidx[(b*TT+to)*MM + m];
        const float* ap = xyzs + ((size_t)(b*TT+to)*NN + aidx)*3;
        float ax = ap[0], ay = ap[1], az = ap[2];
        int* dst = g_ball + ((((size_t)(b*TT+to))*3 + i)*MM + m)*KK;
        int cnt = 0, first = 0; bool none = true;
        for (int base = 0; base < NN && cnt < KK; base += 32) {
            int p = base + lane;
            float dd = sq3(px[p]-ax, py[p]-ay, pz[p]-az);
            bool in = dd < RR;
            unsigned mask = __ballot_sync(0xffffffffu, in);
            if (mask) {
                if (none) { first = base + __ffs(mask) - 1; none = false; }
                int off = cnt + __popc(mask & ((1u << lane) - 1u));
                if (in && off < KK) dst[off] = p;
                cnt = min(KK, cnt + __popc(mask));
            }
        }
        int pad = none ? 0 : first;
        if (lane >= cnt) dst[lane] = pad;
    }
}

// ---------------- Kernel D: grouped MLP + maxpool + temporal sum -------------------
// block = 128 threads (thread = output channel c1), 32 anchors per block
__global__ __launch_bounds__(128) void conv_kernel(const float* __restrict__ xyzs,
                                                   const float* __restrict__ Wd,
                                                   const float* __restrict__ W1,
                                                   float* __restrict__ outf) {
    __shared__ __align__(16) float sFeat[KK*C0V];   // 8 KB
    __shared__ float4 sWd4[C0V];                    // 1 KB
    __shared__ float4 sD4[KK];                      // 512 B
    __shared__ int    sIdx[KK];
    __shared__ float  sAcc[C1V*33];                 // padded, 16.9 KB

    int blk = blockIdx.x;
    int bt  = blk >> 5;
    int m0  = (blk & 31) * 32;
    int b   = bt / TT, to = bt % TT;
    int tid = threadIdx.x;

    // W1 row in registers (thread = c1)
    float4 w1[16];
    const float4* W1r = (const float4*)(W1 + (size_t)tid*C0V);
    #pragma unroll
    for (int j = 0; j < 16; j++) w1[j] = W1r[j];
    if (tid < C0V) sWd4[tid] = ((const float4*)Wd)[tid];
    __syncthreads();

    for (int ml = 0; ml < 32; ml++) {
        int m = m0 + ml;
        int aidx = g_aidx[bt*MM + m];
        const float* ap = xyzs + ((size_t)bt*NN + aidx)*3;
        float ax = ap[0], ay = ap[1], az = ap[2];
        float acc = 0.f;
        #pragma unroll 1
        for (int i = 0; i < 3; i++) {
            int ti = min(max(to + i - 1, 0), TT-1);
            const int* ib = g_ball + (((size_t)bt*3 + i)*MM + m)*KK;
            if (tid < KK) {
                int p = ib[tid];
                sIdx[tid] = p;
                const float* pp = xyzs + ((size_t)(b*TT+ti)*NN + p)*3;
                sD4[tid] = make_float4(pp[0]-ax, pp[1]-ay, pp[2]-az, (float)(i-1));
            }
            __syncthreads();
            const float* xfb = g_xf + ((size_t)(b*TT+ti))*NN*C0V;
            #pragma unroll
            for (int r = 0; r < 16; r++) {
                int e = r*128 + tid;
                int k = e >> 6, c0 = e & 63;
                float  ff = xfb[(size_t)sIdx[k]*C0V + c0];  // coalesced gather
                float4 wd = sWd4[c0];
                float4 d4 = sD4[k];
                float df = wd.x*d4.x + wd.y*d4.y + wd.z*d4.z + wd.w*d4.w;
                sFeat[k*C0V + c0] = ff + fmaxf(df, 0.f);
            }
            __syncthreads();
            float best = -1e30f;
            #pragma unroll 2
            for (int k = 0; k < KK; k++) {
                const float4* f4 = (const float4*)(sFeat + k*C0V);
                float s0 = 0.f, s1 = 0.f, s2 = 0.f, s3 = 0.f;
                #pragma unroll
                for (int j = 0; j < 16; j++) {
                    float4 f = f4[j];                 // uniform broadcast LDS.128
                    s0 = fmaf(w1[j].x, f.x, s0);
                    s1 = fmaf(w1[j].y, f.y, s1);
                    s2 = fmaf(w1[j].z, f.z, s2);
                    s3 = fmaf(w1[j].w, f.w, s3);
                }
                best = fmaxf(best, (s0 + s1) + (s2 + s3));
            }
            acc += fmaxf(best, 0.f);                  // relu-then-max == max(0, max)
            __syncthreads();
        }
        sAcc[tid*33 + ml] = acc;
    }
    __syncthreads();
    // coalesced transposed store: out[b,to,c1,m]
    float* ob = outf + ((size_t)bt*C1V)*MM + m0;
    #pragma unroll 4
    for (int j = 0; j < 32; j++) {
        int e   = j*128 + tid;
        int row = e >> 5, col = e & 31;
        ob[(size_t)row*MM + col] = sAcc[row*33 + col];
    }
}

// ---------------- launch -----------------------------------------------------------
extern "C" void kernel_launch(void* const* d_in, const int* in_sizes, int n_in,
                              void* d_out, int out_size) {
    const float* xyzs = (const float*)d_in[0];   // (4,8,4096,3)
    const float* feat = (const float*)d_in[1];   // (4,8,64,4096)
    const float* Wd   = (const float*)d_in[2];   // (64,4)
    const float* Wf   = (const float*)d_in[3];   // (64,64)
    const float* W1   = (const float*)d_in[4];   // (128,64)
    float* out_xyz = (float*)d_out;                          // (4,8,1024,3)
    float* out_f   = (float*)d_out + (size_t)BB*TT*MM*3;     // (4,8,128,1024)

    xf_kernel<<<dim3(BB*TT, NN/64), 256>>>(feat, Wf);
    fps_kernel<<<BB*TT, 1024>>>(xyzs);
    anchor_kernel<<<(BB*TT*MM + 255)/256, 256>>>(xyzs, out_xyz);
    ball_kernel<<<dim3(BB*TT*3, 4), 256, 3*NN*sizeof(float)>>>(xyzs);
    conv_kernel<<<BB*TT*32, 128>>>(xyzs, Wd, W1, out_f);
}

// round 4
// speedup vs baseline: 1.4832x; 1.4832x over previous
#include <cuda_runtime.h>
#include <cstdint>

#define BB   4
#define TT   8
#define NN   4096
#define CIN  64
#define C0V  64
#define C1V  128
#define MM   1024
#define KK   32

// ---------------- scratch (device globals; no allocation allowed) ----------------
__device__ int   g_aidx[BB*TT*MM];            // FPS anchor indices
__device__ int   g_ball[BB*TT*3*MM*KK];       // ball query indices      (12 MB)
__device__ float g_xf[(size_t)BB*TT*NN*C0V];  // relu(Wf . f) per point  (33.5 MB)

// exact (non-contracted) squared distance, matches XLA elementwise+reduce order
__device__ __forceinline__ float sq3(float dx, float dy, float dz) {
    return __fadd_rn(__fadd_rn(__fmul_rn(dx,dx), __fmul_rn(dy,dy)), __fmul_rn(dz,dz));
}

__device__ __forceinline__ uint32_t f2tf32(float x) {
    uint32_t u;
    asm("cvt.rna.tf32.f32 %0, %1;" : "=r"(u) : "f"(x));
    return u;
}

__device__ __forceinline__ void mma_tf32(float c[4], const uint32_t a[4], const uint32_t b[2]) {
    asm volatile(
        "mma.sync.aligned.m16n8k8.row.col.f32.tf32.tf32.f32 "
        "{%0,%1,%2,%3}, {%4,%5,%6,%7}, {%8,%9}, {%0,%1,%2,%3};"
        : "+f"(c[0]), "+f"(c[1]), "+f"(c[2]), "+f"(c[3])
        : "r"(a[0]), "r"(a[1]), "r"(a[2]), "r"(a[3]), "r"(b[0]), "r"(b[1]));
}

// ---------------- Kernel A: Xf[b,t,p,c0] = relu(sum_c Wf[c0,c] * feat[b,t,c,p]) ----
__global__ __launch_bounds__(256) void xf_kernel(const float* __restrict__ feat,
                                                 const float* __restrict__ Wf) {
    int bt = blockIdx.x;          // 0..31
    int p0 = blockIdx.y * 64;     // point tile
    __shared__ float sWfT[CIN*C0V];   // [c][o]
    __shared__ float sF[CIN*64];      // [c][p]
    int tid = threadIdx.x;
    for (int e = tid; e < CIN*C0V; e += 256) {
        int o = e / CIN, c = e % CIN;
        sWfT[c*C0V + o] = Wf[e];
    }
    const float* fb = feat + (size_t)bt*CIN*NN + p0;
    for (int e = tid; e < CIN*64; e += 256) {
        int c = e >> 6, p = e & 63;
        sF[e] = fb[(size_t)c*NN + p];
    }
    __syncthreads();
    float* xb = g_xf + ((size_t)bt*NN + p0)*C0V;
    #pragma unroll 4
    for (int r = 0; r < 16; r++) {
        int e = r*256 + tid;
        int p = e >> 6, o = e & 63;
        float s = 0.f;
        #pragma unroll
        for (int c = 0; c < CIN; c++)
            s = fmaf(sWfT[c*C0V + o], sF[c*64 + p], s);
        xb[(size_t)p*C0V + o] = fmaxf(s, 0.f);
    }
}

// ---------------- Kernel B: furthest point sampling, one block per (b, frame) ------
// One __syncthreads per iteration. Argmax carried as packed 64-bit key:
// (float-bits(dist)<<32) | ~idx  -> max == larger dist, ties -> smaller index.
// Every warp redundantly reduces the 32 warp winners (no serialized warp-0 stage).
__global__ __launch_bounds__(1024) void fps_kernel(const float* __restrict__ xyzs) {
    __shared__ unsigned long long sKey[2][32];
    int bt  = blockIdx.x;
    int tid = threadIdx.x;
    const float* xb = xyzs + (size_t)bt*NN*3;

    int   i0 = tid, i1 = tid+1024, i2 = tid+2048, i3 = tid+3072;
    float x0=xb[i0*3+0], y0=xb[i0*3+1], z0=xb[i0*3+2];
    float x1=xb[i1*3+0], y1=xb[i1*3+1], z1=xb[i1*3+2];
    float x2=xb[i2*3+0], y2=xb[i2*3+1], z2=xb[i2*3+2];
    float x3=xb[i3*3+0], y3=xb[i3*3+1], z3=xb[i3*3+2];
    float d0=1e10f, d1=1e10f, d2=1e10f, d3=1e10f;

    int* aout = g_aidx + bt*MM;
    if (tid == 0) aout[0] = 0;
    // coords of current "last" point (index 0): broadcast L1 load
    float lx = xb[0], ly = xb[1], lz = xb[2];
    int lane = tid & 31, wid = tid >> 5;

    for (int it = 1; it < MM; it++) {
        d0 = fminf(d0, sq3(x0-lx, y0-ly, z0-lz));
        d1 = fminf(d1, sq3(x1-lx, y1-ly, z1-lz));
        d2 = fminf(d2, sq3(x2-lx, y2-ly, z2-lz));
        d3 = fminf(d3, sq3(x3-lx, y3-ly, z3-lz));
        unsigned long long k0 = ((unsigned long long)__float_as_uint(d0) << 32) | (uint32_t)~(uint32_t)i0;
        unsigned long long k1 = ((unsigned long long)__float_as_uint(d1) << 32) | (uint32_t)~(uint32_t)i1;
        unsigned long long k2 = ((unsigned long long)__float_as_uint(d2) << 32) | (uint32_t)~(uint32_t)i2;
        unsigned long long k3 = ((unsigned long long)__float_as_uint(d3) << 32) | (uint32_t)~(uint32_t)i3;
        unsigned long long key = max(max(k0, k1), max(k2, k3));
        #pragma unroll
        for (int o = 16; o > 0; o >>= 1) {
            unsigned long long ok = __shfl_xor_sync(0xffffffffu, key, o);
            if (ok > key) key = ok;
        }
        if (lane == 0) sKey[it & 1][wid] = key;
        __syncthreads();
        unsigned long long bk = sKey[it & 1][lane];
        #pragma unroll
        for (int o = 16; o > 0; o >>= 1) {
            unsigned long long ok = __shfl_xor_sync(0xffffffffu, bk, o);
            if (ok > bk) bk = ok;
        }
        int ix = (int)~(uint32_t)bk;
        if (tid == 0) aout[it] = ix;
        lx = xb[ix*3+0]; ly = xb[ix*3+1]; lz = xb[ix*3+2];   // broadcast L1 hit
    }
}

// ---------------- Kernel E: write new_xyzs (anchor coords) -------------------------
__global__ __launch_bounds__(256) void anchor_kernel(const float* __restrict__ xyzs,
                                                     float* __restrict__ outxyz) {
    int idx = blockIdx.x*256 + threadIdx.x;
    if (idx >= BB*TT*MM) return;
    int bt = idx / MM;
    int a  = g_aidx[idx];
    const float* s = xyzs + ((size_t)bt*NN + a)*3;
    float* d = outxyz + (size_t)idx*3;
    d[0] = s[0]; d[1] = s[1]; d[2] = s[2];
}

// ---------------- Kernel C: ball query (warp per anchor, first-K ascending) --------
// dynamic smem = 49152 B exactly, no static smem in this kernel (48 KB limit OK)
__global__ __launch_bounds__(256) void ball_kernel(const float* __restrict__ xyzs) {
    extern __shared__ float sm[];           // frame ti points (48 KB)
    float* px = sm; float* py = sm + NN; float* pz = sm + 2*NN;
    int g  = blockIdx.x;                    // (b, to, i)
    int b  = g / (TT*3);
    int r  = g % (TT*3);
    int to = r / 3, i = r % 3;
    int ti = min(max(to + i - 1, 0), TT-1);
    int tid = threadIdx.x;
    const float* fb = xyzs + ((size_t)(b*TT+ti))*NN*3;
    for (int p = tid; p < NN; p += 256) {
        px[p] = fb[p*3+0]; py[p] = fb[p*3+1]; pz[p] = fb[p*3+2];
    }
    __syncthreads();
    const float RR = (float)(0.2*0.2);
    int warp = tid >> 5, lane = tid & 31;
    for (int mi = 0; mi < 16; mi++) {
        int m = (blockIdx.y*8 + warp)*16 + mi;
        int aidx = g_aidx[(b*TT+to)*MM + m];
        const float* ap = xyzs + ((size_t)(b*TT+to)*NN + aidx)*3;
        float ax = ap[0], ay = ap[1], az = ap[2];
        int* dst = g_ball + ((((size_t)(b*TT+to))*3 + i)*MM + m)*KK;
        int cnt = 0, first = 0; bool none = true;
        for (int base = 0; base < NN && cnt < KK; base += 32) {
            int p = base + lane;
            float dd = sq3(px[p]-ax, py[p]-ay, pz[p]-az);
            bool in = dd < RR;
            unsigned mask = __ballot_sync(0xffffffffu, in);
            if (mask) {
                if (none) { first = base + __ffs(mask) - 1; none = false; }
                int off = cnt + __popc(mask & ((1u << lane) - 1u));
                if (in && off < KK) dst[off] = p;
                cnt = min(KK, cnt + __popc(mask));
            }
        }
        int pad = none ? 0 : first;
        if (lane >= cnt) dst[lane] = pad;
    }
}

// ---------------- Kernel D: grouped MLP + maxpool + temporal sum (tf32 tensor core)
// block = 128 threads (4 warps), warp w owns output-channel chunk [32w, 32w+32).
// Per (anchor m, frame i): A = feat[32k x 64c0] (tf32, smem, row stride 68 ->
// conflict-free fragment LDS), B = W1^T chunk held entirely in registers.
// GEMM via mma.sync.m16n8k8.tf32, maxpool over k done on D fragments via shfl.
__global__ __launch_bounds__(128) void conv_kernel(const float* __restrict__ xyzs,
                                                   const float* __restrict__ Wd,
                                                   const float* __restrict__ W1,
                                                   float* __restrict__ outf) {
    __shared__ uint32_t sFeat[KK*68];               // 8.5 KB, tf32 bits, stride 68
    __shared__ float4   sWd4[C0V];                  // 1 KB
    __shared__ float4   sD4[KK];
    __shared__ int      sIdx[KK];
    __shared__ float    sAcc[C1V*33];               // 16.9 KB

    int blk = blockIdx.x;
    int bt  = blk >> 5;
    int m0  = (blk & 31) * 32;
    int b   = bt / TT, to = bt % TT;
    int tid = threadIdx.x;
    int wid = tid >> 5, lane = tid & 31;
    int l4  = lane >> 2, lr = lane & 3;
    int warpN = wid * 32;

    // B fragments: W1^T[k][n] for this warp's 32 output channels (64 regs)
    uint32_t bf[8][4][2];
    #pragma unroll
    for (int kt = 0; kt < 8; kt++) {
        #pragma unroll
        for (int nt = 0; nt < 4; nt++) {
            int n  = warpN + nt*8 + l4;
            int k0 = kt*8 + lr;
            bf[kt][nt][0] = f2tf32(W1[n*C0V + k0]);
            bf[kt][nt][1] = f2tf32(W1[n*C0V + k0 + 4]);
        }
    }
    if (tid < C0V) sWd4[tid] = ((const float4*)Wd)[tid];
    __syncthreads();

    for (int ml = 0; ml < 32; ml++) {
        int m = m0 + ml;
        int aidx = g_aidx[bt*MM + m];
        const float* ap = xyzs + ((size_t)bt*NN + aidx)*3;
        float ax = ap[0], ay = ap[1], az = ap[2];
        float acc0 = 0.f, acc1 = 0.f;
        #pragma unroll 1
        for (int i = 0; i < 3; i++) {
            int ti = min(max(to + i - 1, 0), TT-1);
            const int* ib = g_ball + (((size_t)bt*3 + i)*MM + m)*KK;
            if (tid < KK) {
                int p = ib[tid];
                sIdx[tid] = p;
                const float* pp = xyzs + ((size_t)(b*TT+ti)*NN + p)*3;
                sD4[tid] = make_float4(pp[0]-ax, pp[1]-ay, pp[2]-az, (float)(i-1));
            }
            __syncthreads();
            const float* xfb = g_xf + ((size_t)(b*TT+ti))*NN*C0V;
            #pragma unroll
            for (int r = 0; r < 16; r++) {
                int e = r*128 + tid;
                int k = e >> 6, c0 = e & 63;
                float  ff = xfb[(size_t)sIdx[k]*C0V + c0];   // coalesced gather
                float4 wd = sWd4[c0];
                float4 d4 = sD4[k];
                float df = wd.x*d4.x + wd.y*d4.y + wd.z*d4.z + wd.w*d4.w;
                sFeat[k*68 + c0] = f2tf32(ff + fmaxf(df, 0.f));
            }
            __syncthreads();

            float c[2][4][4] = {};
            #pragma unroll
            for (int kt = 0; kt < 8; kt++) {
                uint32_t a[2][4];
                #pragma unroll
                for (int mt = 0; mt < 2; mt++) {
                    int row = mt*16 + l4;
                    int col = kt*8 + lr;
                    a[mt][0] = sFeat[row*68 + col];
                    a[mt][1] = sFeat[(row+8)*68 + col];
                    a[mt][2] = sFeat[row*68 + col + 4];
                    a[mt][3] = sFeat[(row+8)*68 + col + 4];
                }
                #pragma unroll
                for (int mt = 0; mt < 2; mt++)
                    #pragma unroll
                    for (int nt = 0; nt < 4; nt++)
                        mma_tf32(c[mt][nt], a[mt], bf[kt][nt]);
            }
            // maxpool over the 32 k rows, then relu, accumulate over frames
            #pragma unroll
            for (int nt = 0; nt < 4; nt++) {
                float v0 = fmaxf(fmaxf(c[0][nt][0], c[0][nt][2]),
                                 fmaxf(c[1][nt][0], c[1][nt][2]));
                float v1 = fmaxf(fmaxf(c[0][nt][1], c[0][nt][3]),
                                 fmaxf(c[1][nt][1], c[1][nt][3]));
                #pragma unroll
                for (int o = 4; o <= 16; o <<= 1) {
                    v0 = fmaxf(v0, __shfl_xor_sync(0xffffffffu, v0, o));
                    v1 = fmaxf(v1, __shfl_xor_sync(0xffffffffu, v1, o));
                }
                if (l4 == nt) { acc0 += fmaxf(v0, 0.f); acc1 += fmaxf(v1, 0.f); }
            }
            __syncthreads();    // protect sIdx/sD4/sFeat for next frame
        }
        if (lane < 16) {
            int c1 = warpN + l4*8 + 2*lr;
            sAcc[c1*33 + ml]     = acc0;
            sAcc[(c1+1)*33 + ml] = acc1;
        }
    }
    __syncthreads();
    // coalesced transposed store: out[b,to,c1,m]
    float* ob = outf + ((size_t)bt*C1V)*MM + m0;
    #pragma unroll 4
    for (int j = 0; j < 32; j++) {
        int e   = j*128 + tid;
        int row = e >> 5, col = e & 31;
        ob[(size_t)row*MM + col] = sAcc[row*33 + col];
    }
}

// ---------------- launch -----------------------------------------------------------
extern "C" void kernel_launch(void* const* d_in, const int* in_sizes, int n_in,
                              void* d_out, int out_size) {
    const float* xyzs = (const float*)d_in[0];   // (4,8,4096,3)
    const float* feat = (const float*)d_in[1];   // (4,8,64,4096)
    const float* Wd   = (const float*)d_in[2];   // (64,4)
    const float* Wf   = (const float*)d_in[3];   // (64,64)
    const float* W1   = (const float*)d_in[4];   // (128,64)
    float* out_xyz = (float*)d_out;                          // (4,8,1024,3)
    float* out_f   = (float*)d_out + (size_t)BB*TT*MM*3;     // (4,8,128,1024)

    xf_kernel<<<dim3(BB*TT, NN/64), 256>>>(feat, Wf);
    fps_kernel<<<BB*TT, 1024>>>(xyzs);
    anchor_kernel<<<(BB*TT*MM + 255)/256, 256>>>(xyzs, out_xyz);
    ball_kernel<<<dim3(BB*TT*3, 8), 256, 3*NN*sizeof(float)>>>(xyzs);
    conv_kernel<<<BB*TT*32, 128>>>(xyzs, Wd, W1, out_f);
}

// round 5
// speedup vs baseline: 1.6382x; 1.1045x over previous
#include <cuda_runtime.h>
#include <cstdint>

#define BB   4
#define TT   8
#define NN   4096
#define CIN  64
#define C0V  64
#define C1V  128
#define MM   1024
#define KK   32

// ---------------- scratch (device globals; no allocation allowed) ----------------
__device__ int   g_aidx[BB*TT*MM];            // FPS anchor indices
__device__ int   g_ball[BB*TT*3*MM*KK];       // ball query indices      (12 MB)
__device__ float g_xf[(size_t)BB*TT*NN*C0V];  // relu(Wf . f) per point  (33.5 MB)

// exact (non-contracted) squared distance, matches XLA elementwise+reduce order
__device__ __forceinline__ float sq3(float dx, float dy, float dz) {
    return __fadd_rn(__fadd_rn(__fmul_rn(dx,dx), __fmul_rn(dy,dy)), __fmul_rn(dz,dz));
}

__device__ __forceinline__ uint32_t f2tf32(float x) {
    uint32_t u;
    asm("cvt.rna.tf32.f32 %0, %1;" : "=r"(u) : "f"(x));
    return u;
}

__device__ __forceinline__ void mma_tf32(float c[4], const uint32_t a[4], const uint32_t b[2]) {
    asm volatile(
        "mma.sync.aligned.m16n8k8.row.col.f32.tf32.tf32.f32 "
        "{%0,%1,%2,%3}, {%4,%5,%6,%7}, {%8,%9}, {%0,%1,%2,%3};"
        : "+f"(c[0]), "+f"(c[1]), "+f"(c[2]), "+f"(c[3])
        : "r"(a[0]), "r"(a[1]), "r"(a[2]), "r"(a[3]), "r"(b[0]), "r"(b[1]));
}

// ---------------- Kernel A: Xf[b,t,p,c0] = relu(sum_c Wf[c0,c] * feat[b,t,c,p]) ----
__global__ __launch_bounds__(256) void xf_kernel(const float* __restrict__ feat,
                                                 const float* __restrict__ Wf) {
    int bt = blockIdx.x;          // 0..31
    int p0 = blockIdx.y * 64;     // point tile
    __shared__ float sWfT[CIN*C0V];   // [c][o]
    __shared__ float sF[CIN*64];      // [c][p]
    int tid = threadIdx.x;
    for (int e = tid; e < CIN*C0V; e += 256) {
        int o = e / CIN, c = e % CIN;
        sWfT[c*C0V + o] = Wf[e];
    }
    const float* fb = feat + (size_t)bt*CIN*NN + p0;
    for (int e = tid; e < CIN*64; e += 256) {
        int c = e >> 6, p = e & 63;
        sF[e] = fb[(size_t)c*NN + p];
    }
    __syncthreads();
    float* xb = g_xf + ((size_t)bt*NN + p0)*C0V;
    #pragma unroll 4
    for (int r = 0; r < 16; r++) {
        int e = r*256 + tid;
        int p = e >> 6, o = e & 63;
        float s = 0.f;
        #pragma unroll
        for (int c = 0; c < CIN; c++)
            s = fmaf(sWfT[c*C0V + o], sF[c*64 + p], s);
        xb[(size_t)p*C0V + o] = fmaxf(s, 0.f);
    }
}

// ---------------- Kernel B: furthest point sampling, one block per (b, frame) ------
__global__ __launch_bounds__(1024) void fps_kernel(const float* __restrict__ xyzs) {
    __shared__ unsigned long long sKey[2][32];
    int bt  = blockIdx.x;
    int tid = threadIdx.x;
    const float* xb = xyzs + (size_t)bt*NN*3;

    int   i0 = tid, i1 = tid+1024, i2 = tid+2048, i3 = tid+3072;
    float x0=xb[i0*3+0], y0=xb[i0*3+1], z0=xb[i0*3+2];
    float x1=xb[i1*3+0], y1=xb[i1*3+1], z1=xb[i1*3+2];
    float x2=xb[i2*3+0], y2=xb[i2*3+1], z2=xb[i2*3+2];
    float x3=xb[i3*3+0], y3=xb[i3*3+1], z3=xb[i3*3+2];
    float d0=1e10f, d1=1e10f, d2=1e10f, d3=1e10f;

    int* aout = g_aidx + bt*MM;
    if (tid == 0) aout[0] = 0;
    float lx = xb[0], ly = xb[1], lz = xb[2];
    int lane = tid & 31, wid = tid >> 5;

    for (int it = 1; it < MM; it++) {
        d0 = fminf(d0, sq3(x0-lx, y0-ly, z0-lz));
        d1 = fminf(d1, sq3(x1-lx, y1-ly, z1-lz));
        d2 = fminf(d2, sq3(x2-lx, y2-ly, z2-lz));
        d3 = fminf(d3, sq3(x3-lx, y3-ly, z3-lz));
        unsigned long long k0 = ((unsigned long long)__float_as_uint(d0) << 32) | (uint32_t)~(uint32_t)i0;
        unsigned long long k1 = ((unsigned long long)__float_as_uint(d1) << 32) | (uint32_t)~(uint32_t)i1;
        unsigned long long k2 = ((unsigned long long)__float_as_uint(d2) << 32) | (uint32_t)~(uint32_t)i2;
        unsigned long long k3 = ((unsigned long long)__float_as_uint(d3) << 32) | (uint32_t)~(uint32_t)i3;
        unsigned long long key = max(max(k0, k1), max(k2, k3));
        #pragma unroll
        for (int o = 16; o > 0; o >>= 1) {
            unsigned long long ok = __shfl_xor_sync(0xffffffffu, key, o);
            if (ok > key) key = ok;
        }
        if (lane == 0) sKey[it & 1][wid] = key;
        __syncthreads();
        unsigned long long bk = sKey[it & 1][lane];
        #pragma unroll
        for (int o = 16; o > 0; o >>= 1) {
            unsigned long long ok = __shfl_xor_sync(0xffffffffu, bk, o);
            if (ok > bk) bk = ok;
        }
        int ix = (int)~(uint32_t)bk;
        if (tid == 0) aout[it] = ix;
        lx = xb[ix*3+0]; ly = xb[ix*3+1]; lz = xb[ix*3+2];   // broadcast L1 hit
    }
}

// ---------------- Kernel E: write new_xyzs (anchor coords) -------------------------
__global__ __launch_bounds__(256) void anchor_kernel(const float* __restrict__ xyzs,
                                                     float* __restrict__ outxyz) {
    int idx = blockIdx.x*256 + threadIdx.x;
    if (idx >= BB*TT*MM) return;
    int bt = idx / MM;
    int a  = g_aidx[idx];
    const float* s = xyzs + ((size_t)bt*NN + a)*3;
    float* d = outxyz + (size_t)idx*3;
    d[0] = s[0]; d[1] = s[1]; d[2] = s[2];
}

// ---------------- Kernel C: ball query (warp per anchor, first-K ascending) --------
__global__ __launch_bounds__(256) void ball_kernel(const float* __restrict__ xyzs) {
    extern __shared__ float sm[];           // frame ti points (48 KB)
    float* px = sm; float* py = sm + NN; float* pz = sm + 2*NN;
    int g  = blockIdx.x;                    // (b, to, i)
    int b  = g / (TT*3);
    int r  = g % (TT*3);
    int to = r / 3, i = r % 3;
    int ti = min(max(to + i - 1, 0), TT-1);
    int tid = threadIdx.x;
    const float* fb = xyzs + ((size_t)(b*TT+ti))*NN*3;
    for (int p = tid; p < NN; p += 256) {
        px[p] = fb[p*3+0]; py[p] = fb[p*3+1]; pz[p] = fb[p*3+2];
    }
    __syncthreads();
    const float RR = (float)(0.2*0.2);
    int warp = tid >> 5, lane = tid & 31;
    for (int mi = 0; mi < 16; mi++) {
        int m = (blockIdx.y*8 + warp)*16 + mi;
        int aidx = g_aidx[(b*TT+to)*MM + m];
        const float* ap = xyzs + ((size_t)(b*TT+to)*NN + aidx)*3;
        float ax = ap[0], ay = ap[1], az = ap[2];
        int* dst = g_ball + ((((size_t)(b*TT+to))*3 + i)*MM + m)*KK;
        int cnt = 0, first = 0; bool none = true;
        for (int base = 0; base < NN && cnt < KK; base += 32) {
            int p = base + lane;
            float dd = sq3(px[p]-ax, py[p]-ay, pz[p]-az);
            bool in = dd < RR;
            unsigned mask = __ballot_sync(0xffffffffu, in);
            if (mask) {
                if (none) { first = base + __ffs(mask) - 1; none = false; }
                int off = cnt + __popc(mask & ((1u << lane) - 1u));
                if (in && off < KK) dst[off] = p;
                cnt = min(KK, cnt + __popc(mask));
            }
        }
        int pad = none ? 0 : first;
        if (lane >= cnt) dst[lane] = pad;
    }
}

// ---------------- Kernel D: grouped MLP + maxpool + temporal sum (tf32, fused) -----
// 256 threads / 8 warps. Per anchor: one M=96 (3 frames x 32 nbrs), K=64, N=128 GEMM.
// warp = (mi = wid>>2 in {0,1}: m-tiles 3mi..3mi+2 ; nq = wid&3: channels nq*32..+32)
// Frame rows: 0-31 frame0, 32-63 frame1, 64-95 frame2. Frame1 straddles warps ->
// per-warp partial maxes combined through sPool.
__global__ __launch_bounds__(256) void conv_kernel(const float* __restrict__ xyzs,
                                                   const float* __restrict__ Wd,
                                                   const float* __restrict__ W1,
                                                   float* __restrict__ outf) {
    __shared__ uint32_t sFeat[96*68];               // 26.1 KB, tf32 bits
    __shared__ float4   sWd4[C0V];                  // 1 KB
    __shared__ float4   sD4[96];                    // 1.5 KB
    __shared__ int      sIdx[96];
    __shared__ float    sPool[4][C1V];              // 2 KB  (f0relu, f1a, f1b, f2relu)
    __shared__ float    sAcc[C1V*33];               // 16.9 KB   -> total 48.0 KB

    int blk = blockIdx.x;
    int bt  = blk >> 5;
    int m0  = (blk & 31) * 32;
    int b   = bt / TT, to = bt % TT;
    int tid = threadIdx.x;
    int wid = tid >> 5, lane = tid & 31;
    int l4  = lane >> 2, lr = lane & 3;
    int mi  = wid >> 2, nq = wid & 3;
    int warpN = nq * 32;

    // B fragments: W1^T chunk for this warp's 32 output channels (64 regs)
    uint32_t bf[8][4][2];
    #pragma unroll
    for (int kt = 0; kt < 8; kt++) {
        #pragma unroll
        for (int nt = 0; nt < 4; nt++) {
            int n  = warpN + nt*8 + l4;
            int k0 = kt*8 + lr;
            bf[kt][nt][0] = f2tf32(W1[n*C0V + k0]);
            bf[kt][nt][1] = f2tf32(W1[n*C0V + k0 + 4]);
        }
    }
    if (tid < C0V) sWd4[tid] = ((const float4*)Wd)[tid];
    __syncthreads();

    for (int ml = 0; ml < 32; ml++) {
        int m = m0 + ml;
        int aidx = g_aidx[bt*MM + m];
        const float* ap = xyzs + ((size_t)bt*NN + aidx)*3;
        float ax = ap[0], ay = ap[1], az = ap[2];

        if (tid < 96) {
            int i = tid >> 5, k = tid & 31;
            int ti = min(max(to + i - 1, 0), TT-1);
            int p = g_ball[(((size_t)bt*3 + i)*MM + m)*KK + k];
            sIdx[tid] = p;
            const float* pp = xyzs + ((size_t)(b*TT+ti)*NN + p)*3;
            sD4[tid] = make_float4(pp[0]-ax, pp[1]-ay, pp[2]-az, (float)(i-1));
        }
        __syncthreads();

        // build feat rows for all 3 frames (96 x 64), 24 elems/thread
        #pragma unroll 4
        for (int r = 0; r < 24; r++) {
            int e = r*256 + tid;
            int row = e >> 6, c0 = e & 63;
            int i = row >> 5;
            int ti = min(max(to + i - 1, 0), TT-1);
            const float* xfb = g_xf + ((size_t)(b*TT+ti))*NN*C0V;
            float  ff = xfb[(size_t)sIdx[row]*C0V + c0];     // coalesced gather
            float4 wd = sWd4[c0];
            float4 d4 = sD4[row];
            float df = wd.x*d4.x + wd.y*d4.y + wd.z*d4.z + wd.w*d4.w;
            sFeat[row*68 + c0] = f2tf32(ff + fmaxf(df, 0.f));
        }
        __syncthreads();

        // fused GEMM: this warp's 3 m-tiles x 4 n-tiles
        float c[3][4][4] = {};
        #pragma unroll
        for (int kt = 0; kt < 8; kt++) {
            uint32_t a[3][4];
            #pragma unroll
            for (int mt = 0; mt < 3; mt++) {
                int row = (mi*3 + mt)*16 + l4;
                int col = kt*8 + lr;
                a[mt][0] = sFeat[row*68 + col];
                a[mt][1] = sFeat[(row+8)*68 + col];
                a[mt][2] = sFeat[row*68 + col + 4];
                a[mt][3] = sFeat[(row+8)*68 + col + 4];
            }
            #pragma unroll
            for (int mt = 0; mt < 3; mt++)
                #pragma unroll
                for (int nt = 0; nt < 4; nt++)
                    mma_tf32(c[mt][nt], a[mt], bf[kt][nt]);
        }

        // per-warp frame maxima -> sPool
        #pragma unroll
        for (int nt = 0; nt < 4; nt++) {
            // per-tile partial maxes (over the 2 row-fragments), cols 2lr / 2lr+1
            float t0v0 = fmaxf(c[0][nt][0], c[0][nt][2]);
            float t0v1 = fmaxf(c[0][nt][1], c[0][nt][3]);
            float t1v0 = fmaxf(c[1][nt][0], c[1][nt][2]);
            float t1v1 = fmaxf(c[1][nt][1], c[1][nt][3]);
            float t2v0 = fmaxf(c[2][nt][0], c[2][nt][2]);
            float t2v1 = fmaxf(c[2][nt][1], c[2][nt][3]);
            // mi=0: pA = frame0 max(tiles0,1), pB = frame1-low (tile2)
            // mi=1: pA = frame1-high (tile3),  pB = frame2 max(tiles4,5)
            float pA0 = (mi == 0) ? fmaxf(t0v0, t1v0) : t0v0;
            float pA1 = (mi == 0) ? fmaxf(t0v1, t1v1) : t0v1;
            float pB0 = (mi == 0) ? t2v0 : fmaxf(t1v0, t2v0);
            float pB1 = (mi == 0) ? t2v1 : fmaxf(t1v1, t2v1);
            #pragma unroll
            for (int o = 4; o <= 16; o <<= 1) {
                pA0 = fmaxf(pA0, __shfl_xor_sync(0xffffffffu, pA0, o));
                pA1 = fmaxf(pA1, __shfl_xor_sync(0xffffffffu, pA1, o));
                pB0 = fmaxf(pB0, __shfl_xor_sync(0xffffffffu, pB0, o));
                pB1 = fmaxf(pB1, __shfl_xor_sync(0xffffffffu, pB1, o));
            }
            if (l4 == 0) {
                int n = warpN + nt*8 + 2*lr;
                if (mi == 0) {
                    sPool[0][n]   = fmaxf(pA0, 0.f);  // relu(frame0 max)
                    sPool[0][n+1] = fmaxf(pA1, 0.f);
                    sPool[1][n]   = pB0;              // frame1 partial (pre-relu)
                    sPool[1][n+1] = pB1;
                } else {
                    sPool[2][n]   = pA0;              // frame1 partial (pre-relu)
                    sPool[2][n+1] = pA1;
                    sPool[3][n]   = fmaxf(pB0, 0.f);  // relu(frame2 max)
                    sPool[3][n+1] = fmaxf(pB1, 0.f);
                }
            }
        }
        __syncthreads();

        // combine: acc = (relu(f0) + relu(f1)) + relu(f2), same order as reference
        if (tid < C1V) {
            float f1 = fmaxf(sPool[1][tid], sPool[2][tid]);
            sAcc[tid*33 + ml] = (sPool[0][tid] + fmaxf(f1, 0.f)) + sPool[3][tid];
        }
        __syncthreads();
    }

    // coalesced transposed store: out[b,to,c1,m]
    float* ob = outf + ((size_t)bt*C1V)*MM + m0;
    #pragma unroll 4
    for (int j = 0; j < 16; j++) {
        int e   = j*256 + tid;
        int row = e >> 5, col = e & 31;
        ob[(size_t)row*MM + col] = sAcc[row*33 + col];
    }
}

// ---------------- launch -----------------------------------------------------------
extern "C" void kernel_launch(void* const* d_in, const int* in_sizes, int n_in,
                              void* d_out, int out_size) {
    const float* xyzs = (const float*)d_in[0];   // (4,8,4096,3)
    const float* feat = (const float*)d_in[1];   // (4,8,64,4096)
    const float* Wd   = (const float*)d_in[2];   // (64,4)
    const float* Wf   = (const float*)d_in[3];   // (64,64)
    const float* W1   = (const float*)d_in[4];   // (128,64)
    float* out_xyz = (float*)d_out;                          // (4,8,1024,3)
    float* out_f   = (float*)d_out + (size_t)BB*TT*MM*3;     // (4,8,128,1024)

    xf_kernel<<<dim3(BB*TT, NN/64), 256>>>(feat, Wf);
    fps_kernel<<<BB*TT, 1024>>>(xyzs);
    anchor_kernel<<<(BB*TT*MM + 255)/256, 256>>>(xyzs, out_xyz);
    ball_kernel<<<dim3(BB*TT*3, 8), 256, 3*NN*sizeof(float)>>>(xyzs);
    conv_kernel<<<BB*TT*32, 256>>>(xyzs, Wd, W1, out_f);
}

// round 6
// speedup vs baseline: 2.3245x; 1.4189x over previous
#include <cuda_runtime.h>
#include <cuda_fp16.h>
#include <cstdint>

#define BB   4
#define TT   8
#define NN   4096
#define CIN  64
#define C0V  64
#define C1V  128
#define MM   1024
#define KK   32

// ---------------- scratch (device globals; no allocation allowed) ----------------
__device__ int   g_aidx[BB*TT*MM];            // FPS anchor indices
__device__ int   g_ball[BB*TT*3*MM*KK];       // ball query indices      (12 MB)
__device__ float g_xf[(size_t)BB*TT*NN*C0V];  // relu(Wf . f) per point  (33.5 MB)

// exact (non-contracted) squared distance, matches XLA elementwise+reduce order
__device__ __forceinline__ float sq3(float dx, float dy, float dz) {
    return __fadd_rn(__fadd_rn(__fmul_rn(dx,dx), __fmul_rn(dy,dy)), __fmul_rn(dz,dz));
}

__device__ __forceinline__ uint32_t packh2(float a, float b) {
    __half2 h = __floats2half2_rn(a, b);
    return *reinterpret_cast<uint32_t*>(&h);
}

__device__ __forceinline__ void mma_f16(float c[4], const uint32_t a[4], const uint32_t b[2]) {
    asm volatile(
        "mma.sync.aligned.m16n8k16.row.col.f32.f16.f16.f32 "
        "{%0,%1,%2,%3}, {%4,%5,%6,%7}, {%8,%9}, {%0,%1,%2,%3};"
        : "+f"(c[0]), "+f"(c[1]), "+f"(c[2]), "+f"(c[3])
        : "r"(a[0]), "r"(a[1]), "r"(a[2]), "r"(a[3]), "r"(b[0]), "r"(b[1]));
}

// ---------------- Kernel A: Xf[b,t,p,c0] = relu(sum_c Wf[c0,c] * feat[b,t,c,p]) ----
__global__ __launch_bounds__(256) void xf_kernel(const float* __restrict__ feat,
                                                 const float* __restrict__ Wf) {
    int bt = blockIdx.x;          // 0..31
    int p0 = blockIdx.y * 64;     // point tile
    __shared__ float sWfT[CIN*C0V];   // [c][o]
    __shared__ float sF[CIN*64];      // [c][p]
    int tid = threadIdx.x;
    for (int e = tid; e < CIN*C0V; e += 256) {
        int o = e / CIN, c = e % CIN;
        sWfT[c*C0V + o] = Wf[e];
    }
    const float* fb = feat + (size_t)bt*CIN*NN + p0;
    for (int e = tid; e < CIN*64; e += 256) {
        int c = e >> 6, p = e & 63;
        sF[e] = fb[(size_t)c*NN + p];
    }
    __syncthreads();
    float* xb = g_xf + ((size_t)bt*NN + p0)*C0V;
    #pragma unroll 4
    for (int r = 0; r < 16; r++) {
        int e = r*256 + tid;
        int p = e >> 6, o = e & 63;
        float s = 0.f;
        #pragma unroll
        for (int c = 0; c < CIN; c++)
            s = fmaf(sWfT[c*C0V + o], sF[c*64 + p], s);
        xb[(size_t)p*C0V + o] = fmaxf(s, 0.f);
    }
}

// ---------------- Kernel B: furthest point sampling, one block per (b, frame) ------
// 512 threads, 8 points/thread. Packed 64-bit argmax keys:
// (float-bits(dist)<<32) | ~idx  -> max == larger dist, ties -> smaller index.
__global__ __launch_bounds__(512) void fps_kernel(const float* __restrict__ xyzs) {
    __shared__ unsigned long long sKey[2][16];
    int bt  = blockIdx.x;
    int tid = threadIdx.x;
    const float* xb = xyzs + (size_t)bt*NN*3;

    float px[8], py[8], pz[8], pd[8];
    #pragma unroll
    for (int j = 0; j < 8; j++) {
        int p = tid + j*512;
        px[j] = xb[p*3+0]; py[j] = xb[p*3+1]; pz[j] = xb[p*3+2];
        pd[j] = 1e10f;
    }

    int* aout = g_aidx + bt*MM;
    if (tid == 0) aout[0] = 0;
    float lx = xb[0], ly = xb[1], lz = xb[2];
    int lane = tid & 31, wid = tid >> 5;

    for (int it = 1; it < MM; it++) {
        unsigned long long key = 0;
        #pragma unroll
        for (int j = 0; j < 8; j++) {
            pd[j] = fminf(pd[j], sq3(px[j]-lx, py[j]-ly, pz[j]-lz));
            unsigned long long k =
                ((unsigned long long)__float_as_uint(pd[j]) << 32) | (uint32_t)~(uint32_t)(tid + j*512);
            if (k > key) key = k;
        }
        #pragma unroll
        for (int o = 16; o > 0; o >>= 1) {
            unsigned long long ok = __shfl_xor_sync(0xffffffffu, key, o);
            if (ok > key) key = ok;
        }
        if (lane == 0) sKey[it & 1][wid] = key;
        __syncthreads();
        unsigned long long bk = sKey[it & 1][lane & 15];
        #pragma unroll
        for (int o = 8; o > 0; o >>= 1) {
            unsigned long long ok = __shfl_xor_sync(0xffffffffu, bk, o);
            if (ok > bk) bk = ok;
        }
        int ix = (int)~(uint32_t)bk;
        if (tid == 0) aout[it] = ix;
        lx = xb[ix*3+0]; ly = xb[ix*3+1]; lz = xb[ix*3+2];   // broadcast L1 hit
    }
}

// ---------------- Kernel E: write new_xyzs (anchor coords) -------------------------
__global__ __launch_bounds__(256) void anchor_kernel(const float* __restrict__ xyzs,
                                                     float* __restrict__ outxyz) {
    int idx = blockIdx.x*256 + threadIdx.x;
    if (idx >= BB*TT*MM) return;
    int bt = idx / MM;
    int a  = g_aidx[idx];
    const float* s = xyzs + ((size_t)bt*NN + a)*3;
    float* d = outxyz + (size_t)idx*3;
    d[0] = s[0]; d[1] = s[1]; d[2] = s[2];
}

// ---------------- Kernel C: ball query (warp per anchor, first-K ascending) --------
__global__ __launch_bounds__(256) void ball_kernel(const float* __restrict__ xyzs) {
    extern __shared__ float sm[];           // frame ti points (48 KB)
    float* px = sm; float* py = sm + NN; float* pz = sm + 2*NN;
    int g  = blockIdx.x;                    // (b, to, i)
    int b  = g / (TT*3);
    int r  = g % (TT*3);
    int to = r / 3, i = r % 3;
    int ti = min(max(to + i - 1, 0), TT-1);
    int tid = threadIdx.x;
    const float* fb = xyzs + ((size_t)(b*TT+ti))*NN*3;
    for (int p = tid; p < NN; p += 256) {
        px[p] = fb[p*3+0]; py[p] = fb[p*3+1]; pz[p] = fb[p*3+2];
    }
    __syncthreads();
    const float RR = (float)(0.2*0.2);
    int warp = tid >> 5, lane = tid & 31;
    for (int mi = 0; mi < 16; mi++) {
        int m = (blockIdx.y*8 + warp)*16 + mi;
        int aidx = g_aidx[(b*TT+to)*MM + m];
        const float* ap = xyzs + ((size_t)(b*TT+to)*NN + aidx)*3;
        float ax = ap[0], ay = ap[1], az = ap[2];
        int* dst = g_ball + ((((size_t)(b*TT+to))*3 + i)*MM + m)*KK;
        int cnt = 0, first = 0; bool none = true;
        for (int base = 0; base < NN && cnt < KK; base += 32) {
            int p = base + lane;
            float dd = sq3(px[p]-ax, py[p]-ay, pz[p]-az);
            bool in = dd < RR;
            unsigned mask = __ballot_sync(0xffffffffu, in);
            if (mask) {
                if (none) { first = base + __ffs(mask) - 1; none = false; }
                int off = cnt + __popc(mask & ((1u << lane) - 1u));
                if (in && off < KK) dst[off] = p;
                cnt = min(KK, cnt + __popc(mask));
            }
        }
        int pad = none ? 0 : first;
        if (lane >= cnt) dst[lane] = pad;
    }
}

// ---------------- Kernel D: grouped MLP + maxpool + temporal sum (fp16 MMA, fused) -
// 256 threads / 8 warps. Per anchor: M=96 (3 frames x 32 nbrs), K=64, N=128 GEMM
// via mma.sync.m16n8k16 fp16 (same 11-bit mantissa as tf32, 2x throughput).
// sFeat row stride = 36 half2 words -> fragment LDS provably conflict-free
// (36 mod 32 = 4 => bank = 4*l4 + lr, all 32 distinct).
__global__ __launch_bounds__(256, 2) void conv_kernel(const float* __restrict__ xyzs,
                                                      const float* __restrict__ Wd,
                                                      const float* __restrict__ W1,
                                                      float* __restrict__ outf) {
    __shared__ uint32_t sFeat[96*36];               // 13.8 KB, half2 words
    __shared__ float4   sWd4[C0V];                  // 1 KB
    __shared__ float4   sD4[96];                    // 1.5 KB
    __shared__ int      sIdx[96];
    __shared__ float    sPool[4][C1V];              // 2 KB
    __shared__ float    sAcc[C1V*33];               // 16.9 KB  -> ~35.7 KB total

    int blk = blockIdx.x;
    int bt  = blk >> 5;
    int m0  = (blk & 31) * 32;
    int b   = bt / TT, to = bt % TT;
    int tid = threadIdx.x;
    int wid = tid >> 5, lane = tid & 31;
    int l4  = lane >> 2, lr = lane & 3;
    int mi  = wid >> 2, nq = wid & 3;
    int warpN = nq * 32;

    // B fragments: fp16 W1^T chunk for this warp's 32 output channels (32 regs)
    uint32_t bf[4][4][2];
    #pragma unroll
    for (int kt = 0; kt < 4; kt++) {
        #pragma unroll
        for (int nt = 0; nt < 4; nt++) {
            int n  = warpN + nt*8 + l4;
            int k0 = kt*16 + lr*2;
            bf[kt][nt][0] = packh2(W1[n*C0V + k0],     W1[n*C0V + k0 + 1]);
            bf[kt][nt][1] = packh2(W1[n*C0V + k0 + 8], W1[n*C0V + k0 + 9]);
        }
    }
    if (tid < C0V) sWd4[tid] = ((const float4*)Wd)[tid];
    __syncthreads();

    for (int ml = 0; ml < 32; ml++) {
        int m = m0 + ml;
        int aidx = g_aidx[bt*MM + m];
        const float* ap = xyzs + ((size_t)bt*NN + aidx)*3;
        float ax = ap[0], ay = ap[1], az = ap[2];

        if (tid < 96) {
            int i = tid >> 5, k = tid & 31;
            int ti = min(max(to + i - 1, 0), TT-1);
            int p = g_ball[(((size_t)bt*3 + i)*MM + m)*KK + k];
            sIdx[tid] = p;
            const float* pp = xyzs + ((size_t)(b*TT+ti)*NN + p)*3;
            sD4[tid] = make_float4(pp[0]-ax, pp[1]-ay, pp[2]-az, (float)(i-1));
        }
        __syncthreads();

        // build feat rows (96 x 64) as half2; 2 channels per thread per round
        #pragma unroll 4
        for (int r = 0; r < 12; r++) {
            int e = r*256 + tid;
            int row = e >> 5, cp = e & 31;            // cp = half2 column pair
            int i = row >> 5;
            int ti = min(max(to + i - 1, 0), TT-1);
            const float* xfb = g_xf + ((size_t)(b*TT+ti))*NN*C0V;
            float2 ff = *(const float2*)(xfb + (size_t)sIdx[row]*C0V + 2*cp);
            float4 wd0 = sWd4[2*cp], wd1 = sWd4[2*cp+1];
            float4 d4 = sD4[row];
            float df0 = wd0.x*d4.x + wd0.y*d4.y + wd0.z*d4.z + wd0.w*d4.w;
            float df1 = wd1.x*d4.x + wd1.y*d4.y + wd1.z*d4.z + wd1.w*d4.w;
            sFeat[row*36 + cp] = packh2(ff.x + fmaxf(df0, 0.f),
                                        ff.y + fmaxf(df1, 0.f));
        }
        __syncthreads();

        // fused GEMM: this warp's 3 m-tiles x 4 n-tiles, K=64 in 4 chunks of 16
        float c[3][4][4] = {};
        #pragma unroll
        for (int kt = 0; kt < 4; kt++) {
            uint32_t a[3][4];
            #pragma unroll
            for (int mt = 0; mt < 3; mt++) {
                int row = (mi*3 + mt)*16 + l4;
                int col = kt*8 + lr;
                a[mt][0] = sFeat[row*36 + col];
                a[mt][1] = sFeat[(row+8)*36 + col];
                a[mt][2] = sFeat[row*36 + col + 4];
                a[mt][3] = sFeat[(row+8)*36 + col + 4];
            }
            #pragma unroll
            for (int mt = 0; mt < 3; mt++)
                #pragma unroll
                for (int nt = 0; nt < 4; nt++)
                    mma_f16(c[mt][nt], a[mt], bf[kt][nt]);
        }

        // per-warp frame maxima -> sPool
        #pragma unroll
        for (int nt = 0; nt < 4; nt++) {
            float t0v0 = fmaxf(c[0][nt][0], c[0][nt][2]);
            float t0v1 = fmaxf(c[0][nt][1], c[0][nt][3]);
            float t1v0 = fmaxf(c[1][nt][0], c[1][nt][2]);
            float t1v1 = fmaxf(c[1][nt][1], c[1][nt][3]);
            float t2v0 = fmaxf(c[2][nt][0], c[2][nt][2]);
            float t2v1 = fmaxf(c[2][nt][1], c[2][nt][3]);
            // mi=0: pA = frame0 max(tiles0,1), pB = frame1-low (tile2)
            // mi=1: pA = frame1-high (tile3),  pB = frame2 max(tiles4,5)
            float pA0 = (mi == 0) ? fmaxf(t0v0, t1v0) : t0v0;
            float pA1 = (mi == 0) ? fmaxf(t0v1, t1v1) : t0v1;
            float pB0 = (mi == 0) ? t2v0 : fmaxf(t1v0, t2v0);
            float pB1 = (mi == 0) ? t2v1 : fmaxf(t1v1, t2v1);
            #pragma unroll
            for (int o = 4; o <= 16; o <<= 1) {
                pA0 = fmaxf(pA0, __shfl_xor_sync(0xffffffffu, pA0, o));
                pA1 = fmaxf(pA1, __shfl_xor_sync(0xffffffffu, pA1, o));
                pB0 = fmaxf(pB0, __shfl_xor_sync(0xffffffffu, pB0, o));
                pB1 = fmaxf(pB1, __shfl_xor_sync(0xffffffffu, pB1, o));
            }
            if (l4 == 0) {
                int n = warpN + nt*8 + 2*lr;
                if (mi == 0) {
                    sPool[0][n]   = fmaxf(pA0, 0.f);  // relu(frame0 max)
                    sPool[0][n+1] = fmaxf(pA1, 0.f);
                    sPool[1][n]   = pB0;              // frame1 partial (pre-relu)
                    sPool[1][n+1] = pB1;
                } else {
                    sPool[2][n]   = pA0;              // frame1 partial (pre-relu)
                    sPool[2][n+1] = pA1;
                    sPool[3][n]   = fmaxf(pB0, 0.f);  // relu(frame2 max)
                    sPool[3][n+1] = fmaxf(pB1, 0.f);
                }
            }
        }
        __syncthreads();

        // combine: acc = (relu(f0) + relu(f1)) + relu(f2), reference order
        if (tid < C1V) {
            float f1 = fmaxf(sPool[1][tid], sPool[2][tid]);
            sAcc[tid*33 + ml] = (sPool[0][tid] + fmaxf(f1, 0.f)) + sPool[3][tid];
        }
        __syncthreads();
    }

    // coalesced transposed store: out[b,to,c1,m]
    float* ob = outf + ((size_t)bt*C1V)*MM + m0;
    #pragma unroll 4
    for (int j = 0; j < 16; j++) {
        int e   = j*256 + tid;
        int row = e >> 5, col = e & 31;
        ob[(size_t)row*MM + col] = sAcc[row*33 + col];
    }
}

// ---------------- launch -----------------------------------------------------------
extern "C" void kernel_launch(void* const* d_in, const int* in_sizes, int n_in,
                              void* d_out, int out_size) {
    const float* xyzs = (const float*)d_in[0];   // (4,8,4096,3)
    const float* feat = (const float*)d_in[1];   // (4,8,64,4096)
    const float* Wd   = (const float*)d_in[2];   // (64,4)
    const float* Wf   = (const float*)d_in[3];   // (64,64)
    const float* W1   = (const float*)d_in[4];   // (128,64)
    float* out_xyz = (float*)d_out;                          // (4,8,1024,3)
    float* out_f   = (float*)d_out + (size_t)BB*TT*MM*3;     // (4,8,128,1024)

    xf_kernel<<<dim3(BB*TT, NN/64), 256>>>(feat, Wf);
    fps_kernel<<<BB*TT, 512>>>(xyzs);
    anchor_kernel<<<(BB*TT*MM + 255)/256, 256>>>(xyzs, out_xyz);
    ball_kernel<<<dim3(BB*TT*3, 8), 256, 3*NN*sizeof(float)>>>(xyzs);
    conv_kernel<<<BB*TT*32, 256>>>(xyzs, Wd, W1, out_f);
}

// round 7
// speedup vs baseline: 2.8091x; 1.2085x over previous
#include <cuda_runtime.h>
#include <cuda_fp16.h>
#include <cstdint>

#define BB   4
#define TT   8
#define NN   4096
#define CIN  64
#define C0V  64
#define C1V  128
#define MM   1024
#define KK   32

__device__ int   g_aidx[BB*TT*MM];
__device__ int   g_ball[BB*TT*3*MM*KK];
__device__ float g_xf[(size_t)BB*TT*NN*C0V];

__device__ __forceinline__ float sq3(float dx, float dy, float dz) {
    return __fadd_rn(__fadd_rn(__fmul_rn(dx,dx), __fmul_rn(dy,dy)), __fmul_rn(dz,dz));
}
__device__ __forceinline__ uint32_t packh2(float a, float b) {
    __half2 h = __floats2half2_rn(a, b);
    return *reinterpret_cast<uint32_t*>(&h);
}
__device__ __forceinline__ void mma_f16(float c[4], const uint32_t a[4], const uint32_t b[2]) {
    asm volatile(
        "mma.sync.aligned.m16n8k16.row.col.f32.f16.f16.f32 "
        "{%0,%1,%2,%3}, {%4,%5,%6,%7}, {%8,%9}, {%0,%1,%2,%3};"
        : "+f"(c[0]), "+f"(c[1]), "+f"(c[2]), "+f"(c[3])
        : "r"(a[0]), "r"(a[1]), "r"(a[2]), "r"(a[3]), "r"(b[0]), "r"(b[1]));
}

// ---------------- Kernel A: Xf = relu(Wf . features) -------------------------------
__global__ __launch_bounds__(256) void xf_kernel(const float* __restrict__ feat,
                                                 const float* __restrict__ Wf) {
    int bt = blockIdx.x;
    int p0 = blockIdx.y * 64;
    __shared__ float sWfT[CIN*C0V];
    __shared__ float sF[CIN*64];
    int tid = threadIdx.x;
    for (int e = tid; e < CIN*C0V; e += 256) {
        int o = e / CIN, c = e % CIN;
        sWfT[c*C0V + o] = Wf[e];
    }
    const float* fb = feat + (size_t)bt*CIN*NN + p0;
    for (int e = tid; e < CIN*64; e += 256) {
        int c = e >> 6, p = e & 63;
        sF[e] = fb[(size_t)c*NN + p];
    }
    __syncthreads();
    float* xb = g_xf + ((size_t)bt*NN + p0)*C0V;
    #pragma unroll 4
    for (int r = 0; r < 16; r++) {
        int e = r*256 + tid;
        int p = e >> 6, o = e & 63;
        float s = 0.f;
        #pragma unroll
        for (int c = 0; c < CIN; c++)
            s = fmaf(sWfT[c*C0V + o], sF[c*64 + p], s);
        xb[(size_t)p*C0V + o] = fmaxf(s, 0.f);
    }
}

// ---------------- Kernel B: FPS (512 thr x 8 pts, packed 64-bit argmax keys) -------
__global__ __launch_bounds__(512) void fps_kernel(const float* __restrict__ xyzs) {
    __shared__ unsigned long long sKey[2][16];
    int bt  = blockIdx.x;
    int tid = threadIdx.x;
    const float* xb = xyzs + (size_t)bt*NN*3;

    float px[8], py[8], pz[8], pd[8];
    #pragma unroll
    for (int j = 0; j < 8; j++) {
        int p = tid + j*512;
        px[j] = xb[p*3+0]; py[j] = xb[p*3+1]; pz[j] = xb[p*3+2];
        pd[j] = 1e10f;
    }
    int* aout = g_aidx + bt*MM;
    if (tid == 0) aout[0] = 0;
    float lx = xb[0], ly = xb[1], lz = xb[2];
    int lane = tid & 31, wid = tid >> 5;

    for (int it = 1; it < MM; it++) {
        unsigned long long key = 0;
        #pragma unroll
        for (int j = 0; j < 8; j++) {
            pd[j] = fminf(pd[j], sq3(px[j]-lx, py[j]-ly, pz[j]-lz));
            unsigned long long k =
                ((unsigned long long)__float_as_uint(pd[j]) << 32) | (uint32_t)~(uint32_t)(tid + j*512);
            if (k > key) key = k;
        }
        #pragma unroll
        for (int o = 16; o > 0; o >>= 1) {
            unsigned long long ok = __shfl_xor_sync(0xffffffffu, key, o);
            if (ok > key) key = ok;
        }
        if (lane == 0) sKey[it & 1][wid] = key;
        __syncthreads();
        unsigned long long bk = sKey[it & 1][lane & 15];
        #pragma unroll
        for (int o = 8; o > 0; o >>= 1) {
            unsigned long long ok = __shfl_xor_sync(0xffffffffu, bk, o);
            if (ok > bk) bk = ok;
        }
        int ix = (int)~(uint32_t)bk;
        if (tid == 0) aout[it] = ix;
        lx = xb[ix*3+0]; ly = xb[ix*3+1]; lz = xb[ix*3+2];
    }
}

// ---------------- Kernel E: new_xyzs ----------------------------------------------
__global__ __launch_bounds__(256) void anchor_kernel(const float* __restrict__ xyzs,
                                                     float* __restrict__ outxyz) {
    int idx = blockIdx.x*256 + threadIdx.x;
    if (idx >= BB*TT*MM) return;
    int bt = idx / MM;
    int a  = g_aidx[idx];
    const float* s = xyzs + ((size_t)bt*NN + a)*3;
    float* d = outxyz + (size_t)idx*3;
    d[0] = s[0]; d[1] = s[1]; d[2] = s[2];
}

// ---------------- Kernel C: ball query, 4 points/lane/iteration --------------------
__global__ __launch_bounds__(256) void ball_kernel(const float* __restrict__ xyzs) {
    extern __shared__ float sm[];
    float* px = sm; float* py = sm + NN; float* pz = sm + 2*NN;
    int g  = blockIdx.x;
    int b  = g / (TT*3);
    int r  = g % (TT*3);
    int to = r / 3, i = r % 3;
    int ti = min(max(to + i - 1, 0), TT-1);
    int tid = threadIdx.x;
    const float* fb = xyzs + ((size_t)(b*TT+ti))*NN*3;
    for (int p = tid; p < NN; p += 256) {
        px[p] = fb[p*3+0]; py[p] = fb[p*3+1]; pz[p] = fb[p*3+2];
    }
    __syncthreads();
    const float RR = (float)(0.2*0.2);
    int warp = tid >> 5, lane = tid & 31;
    unsigned lmask = (1u << lane) - 1u;
    for (int mi = 0; mi < 16; mi++) {
        int m = (blockIdx.y*8 + warp)*16 + mi;
        int aidx = g_aidx[(b*TT+to)*MM + m];
        const float* ap = xyzs + ((size_t)(b*TT+to)*NN + aidx)*3;
        float ax = ap[0], ay = ap[1], az = ap[2];
        int* dst = g_ball + ((((size_t)(b*TT+to))*3 + i)*MM + m)*KK;
        int cnt = 0, first = 0; bool none = true;
        for (int base = 0; base < NN && cnt < KK; base += 128) {
            bool in[4];
            #pragma unroll
            for (int j = 0; j < 4; j++) {
                int p = base + 32*j + lane;
                in[j] = sq3(px[p]-ax, py[p]-ay, pz[p]-az) < RR;
            }
            #pragma unroll
            for (int j = 0; j < 4; j++) {
                unsigned mask = __ballot_sync(0xffffffffu, in[j]);
                if (mask) {
                    if (none) { first = base + 32*j + __ffs(mask) - 1; none = false; }
                    int off = cnt + __popc(mask & lmask);
                    if (in[j] && off < KK) dst[off] = base + 32*j + lane;
                    cnt = min(KK, cnt + __popc(mask));
                }
            }
        }
        int pad = none ? 0 : first;
        if (lane >= cnt) dst[lane] = pad;
    }
}

// ---------------- Kernel D: pipelined fused conv (fp16 MMA) ------------------------
// 3-stage pipeline per anchor ml:
//   S1(ml+2): ball idx + neighbor xyz  -> regs (pre-MMA) -> sIdx/sD4[(ml+2)&1] (post-MMA)
//   S2(ml+1): xf gather -> regs (pre-MMA) -> dfeat+pack -> sFeat[(ml+1)&1] (post-MMA)
//   MMA(ml):  on sFeat[ml&1]; pool -> sPool; 2 syncs/anchor.
__global__ __launch_bounds__(256) void conv_kernel(const float* __restrict__ xyzs,
                                                   const float* __restrict__ Wd,
                                                   const float* __restrict__ W1,
                                                   float* __restrict__ outf) {
    __shared__ uint32_t sFeat[2][96*36];            // 27.6 KB
    __shared__ float4   sWd4[C0V];                  // 1 KB
    __shared__ float4   sD4[2][96];                 // 3 KB
    __shared__ int      sIdx[2][96];
    __shared__ float4   sAnch[32];
    __shared__ float    sPool[4][C1V];              // 2 KB
    __shared__ float    sAcc[C1V*17];               // 8.7 KB (16-anchor chunks)

    int blk = blockIdx.x;
    int bt  = blk >> 5;
    int m0  = (blk & 31) * 32;
    int b   = bt / TT, to = bt % TT;
    int tid = threadIdx.x;
    int lane = tid & 31;
    int l4  = lane >> 2, lr = lane & 3;
    int wd8 = tid >> 5;
    int mi  = wd8 >> 2, nq = wd8 & 3;
    int warpN = nq * 32;

    // W1^T fp16 fragments (32 regs)
    uint32_t bf[4][4][2];
    #pragma unroll
    for (int kt = 0; kt < 4; kt++)
        #pragma unroll
        for (int nt = 0; nt < 4; nt++) {
            int n  = warpN + nt*8 + l4;
            int k0 = kt*16 + lr*2;
            bf[kt][nt][0] = packh2(W1[n*C0V + k0],     W1[n*C0V + k0 + 1]);
            bf[kt][nt][1] = packh2(W1[n*C0V + k0 + 8], W1[n*C0V + k0 + 9]);
        }
    if (tid < C0V) sWd4[tid] = ((const float4*)Wd)[tid];
    if (tid < 32) {
        int aidx = g_aidx[bt*MM + m0 + tid];
        const float* ap = xyzs + ((size_t)bt*NN + aidx)*3;
        sAnch[tid] = make_float4(ap[0], ap[1], ap[2], 0.f);
    }
    __syncthreads();

    int s_i  = tid >> 5;                 // frame for S1 role (tid<96)
    int s_ti = min(max(to + s_i - 1, 0), TT-1);

    // prologue: S1(0), S1(1)
    #pragma unroll
    for (int pm = 0; pm < 2; pm++) {
        if (tid < 96) {
            int k = tid & 31;
            int p = g_ball[(((size_t)bt*3 + s_i)*MM + m0 + pm)*KK + k];
            const float* pp = xyzs + ((size_t)(b*TT+s_ti)*NN + p)*3;
            float4 A = sAnch[pm];
            sIdx[pm][tid] = p;
            sD4[pm][tid] = make_float4(pp[0]-A.x, pp[1]-A.y, pp[2]-A.z, (float)(s_i-1));
        }
    }
    __syncthreads();
    // prologue: S2(0) build sFeat[0]
    {
        int cp = tid & 31, r0 = tid >> 5;
        #pragma unroll
        for (int r = 0; r < 12; r++) {
            int row = r0 + 8*r;
            int i = row >> 5;
            int ti = min(max(to + i - 1, 0), TT-1);
            int idx = sIdx[0][row];
            float2 ff = *(const float2*)(g_xf + ((size_t)(b*TT+ti)*NN + idx)*C0V + 2*cp);
            float4 wd0 = sWd4[2*cp], wd1 = sWd4[2*cp+1];
            float4 d4 = sD4[0][row];
            float df0 = wd0.x*d4.x + wd0.y*d4.y + wd0.z*d4.z + wd0.w*d4.w;
            float df1 = wd1.x*d4.x + wd1.y*d4.y + wd1.z*d4.z + wd1.w*d4.w;
            sFeat[0][row*36 + cp] = packh2(ff.x + fmaxf(df0, 0.f), ff.y + fmaxf(df1, 0.f));
        }
    }
    __syncthreads();

    for (int ml = 0; ml < 32; ml++) {
        int cur = ml & 1;
        // ---- S1(ml+2) load phase ----
        int  s1ml = ml + 2;
        bool act1 = (s1ml < 32) && (tid < 96);
        int   p1 = 0; float p1x=0, p1y=0, p1z=0; float4 A1 = {};
        if (act1) {
            int k = tid & 31;
            p1 = g_ball[(((size_t)bt*3 + s_i)*MM + m0 + s1ml)*KK + k];
            const float* pp = xyzs + ((size_t)(b*TT+s_ti)*NN + p1)*3;
            p1x = pp[0]; p1y = pp[1]; p1z = pp[2];
            A1 = sAnch[s1ml];
        }
        // ---- S2(ml+1) load phase ----
        int  s2ml = ml + 1;
        bool act2 = (s2ml < 32);
        int  cp = tid & 31, r0 = tid >> 5;
        float2 xf2[12];
        if (act2) {
            int nb = s2ml & 1;
            #pragma unroll
            for (int r = 0; r < 12; r++) {
                int row = r0 + 8*r;
                int i = row >> 5;
                int ti = min(max(to + i - 1, 0), TT-1);
                int idx = sIdx[nb][row];
                xf2[r] = *(const float2*)(g_xf + ((size_t)(b*TT+ti)*NN + idx)*C0V + 2*cp);
            }
        }

        // ---- MMA(ml) on sFeat[cur] ----
        float c[3][4][4] = {};
        #pragma unroll
        for (int kt = 0; kt < 4; kt++) {
            uint32_t a[3][4];
            #pragma unroll
            for (int mt = 0; mt < 3; mt++) {
                int row = (mi*3 + mt)*16 + l4;
                int col = kt*8 + lr;
                a[mt][0] = sFeat[cur][row*36 + col];
                a[mt][1] = sFeat[cur][(row+8)*36 + col];
                a[mt][2] = sFeat[cur][row*36 + col + 4];
                a[mt][3] = sFeat[cur][(row+8)*36 + col + 4];
            }
            #pragma unroll
            for (int mt = 0; mt < 3; mt++)
                #pragma unroll
                for (int nt = 0; nt < 4; nt++)
                    mma_f16(c[mt][nt], a[mt], bf[kt][nt]);
        }
        // pool -> sPool
        #pragma unroll
        for (int nt = 0; nt < 4; nt++) {
            float t0v0 = fmaxf(c[0][nt][0], c[0][nt][2]);
            float t0v1 = fmaxf(c[0][nt][1], c[0][nt][3]);
            float t1v0 = fmaxf(c[1][nt][0], c[1][nt][2]);
            float t1v1 = fmaxf(c[1][nt][1], c[1][nt][3]);
            float t2v0 = fmaxf(c[2][nt][0], c[2][nt][2]);
            float t2v1 = fmaxf(c[2][nt][1], c[2][nt][3]);
            float pA0 = (mi == 0) ? fmaxf(t0v0, t1v0) : t0v0;
            float pA1 = (mi == 0) ? fmaxf(t0v1, t1v1) : t0v1;
            float pB0 = (mi == 0) ? t2v0 : fmaxf(t1v0, t2v0);
            float pB1 = (mi == 0) ? t2v1 : fmaxf(t1v1, t2v1);
            #pragma unroll
            for (int o = 4; o <= 16; o <<= 1) {
                pA0 = fmaxf(pA0, __shfl_xor_sync(0xffffffffu, pA0, o));
                pA1 = fmaxf(pA1, __shfl_xor_sync(0xffffffffu, pA1, o));
                pB0 = fmaxf(pB0, __shfl_xor_sync(0xffffffffu, pB0, o));
                pB1 = fmaxf(pB1, __shfl_xor_sync(0xffffffffu, pB1, o));
            }
            if (l4 == 0) {
                int n = warpN + nt*8 + 2*lr;
                if (mi == 0) {
                    sPool[0][n]   = fmaxf(pA0, 0.f);
                    sPool[0][n+1] = fmaxf(pA1, 0.f);
                    sPool[1][n]   = pB0;
                    sPool[1][n+1] = pB1;
                } else {
                    sPool[2][n]   = pA0;
                    sPool[2][n+1] = pA1;
                    sPool[3][n]   = fmaxf(pB0, 0.f);
                    sPool[3][n+1] = fmaxf(pB1, 0.f);
                }
            }
        }

        // ---- S2(ml+1) store phase (gather latency was hidden under MMA) ----
        if (act2) {
            int nb = s2ml & 1;
            #pragma unroll
            for (int r = 0; r < 12; r++) {
                int row = r0 + 8*r;
                float4 wd0 = sWd4[2*cp], wd1 = sWd4[2*cp+1];
                float4 d4 = sD4[nb][row];
                float df0 = wd0.x*d4.x + wd0.y*d4.y + wd0.z*d4.z + wd0.w*d4.w;
                float df1 = wd1.x*d4.x + wd1.y*d4.y + wd1.z*d4.z + wd1.w*d4.w;
                sFeat[nb][row*36 + cp] = packh2(xf2[r].x + fmaxf(df0, 0.f),
                                                xf2[r].y + fmaxf(df1, 0.f));
            }
        }
        // ---- S1(ml+2) store phase ----
        if (act1) {
            int nb = s1ml & 1;
            sIdx[nb][tid] = p1;
            sD4[nb][tid] = make_float4(p1x-A1.x, p1y-A1.y, p1z-A1.z, (float)(s_i-1));
        }
        __syncthreads();

        // combine -> sAcc
        if (tid < C1V) {
            float f1 = fmaxf(sPool[1][tid], sPool[2][tid]);
            sAcc[tid*17 + (ml & 15)] = (sPool[0][tid] + fmaxf(f1, 0.f)) + sPool[3][tid];
        }
        if ((ml & 15) == 15) {
            __syncthreads();
            int mbase = m0 + (ml - 15);
            float* ob = outf + ((size_t)bt*C1V)*MM + mbase;
            #pragma unroll
            for (int j = 0; j < 8; j++) {
                int e = j*256 + tid;
                int row = e >> 4, col = e & 15;
                ob[(size_t)row*MM + col] = sAcc[row*17 + col];
            }
        }
        __syncthreads();
    }
}

// ---------------- launch -----------------------------------------------------------
extern "C" void kernel_launch(void* const* d_in, const int* in_sizes, int n_in,
                              void* d_out, int out_size) {
    const float* xyzs = (const float*)d_in[0];
    const float* feat = (const float*)d_in[1];
    const float* Wd   = (const float*)d_in[2];
    const float* Wf   = (const float*)d_in[3];
    const float* W1   = (const float*)d_in[4];
    float* out_xyz = (float*)d_out;
    float* out_f   = (float*)d_out + (size_t)BB*TT*MM*3;

    xf_kernel<<<dim3(BB*TT, NN/64), 256>>>(feat, Wf);
    fps_kernel<<<BB*TT, 512>>>(xyzs);
    anchor_kernel<<<(BB*TT*MM + 255)/256, 256>>>(xyzs, out_xyz);
    ball_kernel<<<dim3(BB*TT*3, 8), 256, 3*NN*sizeof(float)>>>(xyzs);
    conv_kernel<<<BB*TT*32, 256>>>(xyzs, Wd, W1, out_f);
}